// round 14
// baseline (speedup 1.0000x reference)
#include <cuda_runtime.h>
#include <cuda_fp16.h>
#include <math.h>

#define TQ    2000
#define KIN   400
#define MAXB  64
#define LOG2E 1.4426950408889634f
#define LN2   0.6931471805599453f
#define ANEG  (-1e7f)               // log2-domain sink (finite)
#define PB    0.36787944117144233f  // e^{-1}: unnormalized blank prob

// ctc geometry (numerically proven): 1 pair/thread, 64-state warp window
#define KSTEP 8
#define PPW   24                    // owned pairs per warp = 32 - KSTEP
#define NW    17                    // ceil(401 / 24)
#define NT    (NW * 32)             // 544 threads

#define TTILE 16                    // t-rows per prep tile
#define NTILE 125                   // ceil(1999 / 16): covers t = 1..1999
#define RS    406                   // smem row stride (halfs), conflict-free

__device__ float g_lse[MAXB * TQ];
// e^{attn} fp16, TRANSPOSED: half index = (b*KIN + col)*TQ + (t-1), t>=1
__device__ uint4 g_ptT[(size_t)MAXB * KIN * TQ / 8];
__device__ float g_losses[MAXB];

__device__ __forceinline__ float ex2(float x) {
    float r; asm("ex2.approx.ftz.f32 %0, %1;" : "=f"(r) : "f"(x)); return r;
}
__device__ __forceinline__ float lg2(float x) {
    float r; asm("lg2.approx.ftz.f32 %0, %1;" : "=f"(r) : "f"(x)); return r;
}
__device__ __forceinline__ float lse2f(float a, float b) {
    return fmaxf(a, b) + lg2(1.f + ex2(-fabsf(a - b)));
}
__device__ __forceinline__ float warp_fmax_redux(float x) {
    unsigned uk = __float_as_uint(x);
    uk = uk ^ (unsigned)(((int)uk >> 31) | (int)0x80000000);
    uk = __reduce_max_sync(0xffffffffu, uk);
    uk = uk ^ (unsigned)(((int)(~uk) >> 31) | (int)0x80000000);
    return __uint_as_float(uk);
}

// ---------------------------------------------------------------------------
// Kernel 1: fused LSE + fp16 e^attn TRANSPOSED table.
// Grid (NTILE, B), 256 threads. Tile covers t = t1..t1+15, t1 = 1+16*tile.
// Phase 1: warp w computes rows 2w, 2w+1 (ex2 + masked row sum -> lse),
//          staging halfs in smem. Tile 0 warp 0 also does t=0 (lse only).
// Phase 2: transposed store — per column, 16 consecutive t as 2x STG.128.
// Rows with t >= OL are skipped (their table slots are never converted/used).
// ---------------------------------------------------------------------------
__global__ void prep_kernel(const float* __restrict__ attn,
                            const int* __restrict__ in_lens,
                            const int* __restrict__ out_lens) {
    __shared__ __half tile[TTILE][RS];
    const int b  = blockIdx.y;
    const int t1 = 1 + TTILE * blockIdx.x;
    const int OL = out_lens[b];
    const int L  = in_lens[b];
    const int w    = threadIdx.x >> 5;
    const int lane = threadIdx.x & 31;

    #pragma unroll
    for (int rr = 0; rr < 2; rr++) {
        const int r = w * 2 + rr;
        const int t = t1 + r;
        if (t <= TQ - 1 && t < OL) {
            const float* row = attn + ((size_t)b * TQ + t) * KIN;
            float s = 0.f;
            for (int k = lane; k < KIN; k += 32) {
                const float e = ex2(__ldg(row + k) * LOG2E);
                tile[r][k] = __float2half(e);
                s += (k < L) ? e : 0.f;
            }
            #pragma unroll
            for (int o = 16; o; o >>= 1) s += __shfl_xor_sync(0xffffffffu, s, o);
            if (lane == 0) g_lse[b * TQ + t] = lg2(s + PB);
        }
    }
    if (blockIdx.x == 0 && w == 0) {   // t = 0: lse only (not in table)
        const float* row = attn + (size_t)b * TQ * KIN;
        float s = 0.f;
        for (int k = lane; k < KIN; k += 32) {
            const float e = ex2(__ldg(row + k) * LOG2E);
            s += (k < L) ? e : 0.f;
        }
        #pragma unroll
        for (int o = 16; o; o >>= 1) s += __shfl_xor_sync(0xffffffffu, s, o);
        if (lane == 0) g_lse[b * TQ] = lg2(s + PB);
    }
    __syncthreads();

    // Transposed store: 32B-aligned ((t1-1) % 8 == 0, col base % 8 == 0)
    for (int c = threadIdx.x; c < KIN; c += blockDim.x) {
        unsigned wd[8];
        #pragma unroll
        for (int j = 0; j < 8; j++) {
            const unsigned lo = __half_as_ushort(tile[2 * j][c]);
            const unsigned hi = __half_as_ushort(tile[2 * j + 1][c]);
            wd[j] = lo | (hi << 16);
        }
        const size_t halfbase = ((size_t)b * KIN + c) * TQ + (t1 - 1);
        uint4* dst = g_ptT + (halfbase >> 3);
        dst[0] = make_uint4(wd[0], wd[1], wd[2], wd[3]);
        dst[1] = make_uint4(wd[4], wd[5], wd[6], wd[7]);
    }
}

// ---------------------------------------------------------------------------
// Kernel 2: CTC forward recursion (identical structure to the R13 passing
// kernel; only the emission load path changed to ONE LDG.128 per block from
// the transposed table). 544 threads, one pair (E=2i, O=2i+1) per thread;
// i = w*24 + lane - 8, lanes 0-7 halo. 8 linear steps per barrier, per-warp
// REDUX renorm (64-state window). Unnormalized: subtract S = sum lse2 at end.
// ---------------------------------------------------------------------------
__global__ __launch_bounds__(NT, 1)
void ctc_kernel(const float* __restrict__ attn,
                const int* __restrict__ in_lens,
                const int* __restrict__ out_lens) {
    __shared__ float Es[2][401];
    __shared__ float Os[2][401];
    __shared__ float red[NW];

    const int b    = blockIdx.x;
    const int tid  = threadIdx.x;
    const int L    = in_lens[b];
    const int OL   = out_lens[b];
    const int w    = tid >> 5;
    const int lane = tid & 31;
    const int i    = w * PPW + lane - KSTEP;   // pair index [-8, 416]

    const float* lsebase = g_lse + b * TQ;

    // S = sum_{t<OL} lse2[t]
    {
        float s = 0.f;
        for (int t = tid; t < OL; t += NT) s += lsebase[t];
        #pragma unroll
        for (int o = 16; o; o >>= 1) s += __shfl_xor_sync(0xffffffffu, s, o);
        if (lane == 0) red[w] = s;
    }
    __syncthreads();
    float Sval = 0.f;
    if (tid == 0) {
        #pragma unroll
        for (int k = 0; k < NW; k++) Sval += red[k];
    }

    const bool  tokValid = (i >= 0) && (i < L);
    const float mk = tokValid ? 1.f : 0.f;

    // t=0 init (log2): E(0) = -log2e (blank), O(0) = attn[b][0][0]*log2e
    float E = ANEG, O = ANEG;
    if (i == 0) {
        E = -LOG2E;
        O = __ldg(attn + (size_t)b * TQ * KIN) * LOG2E;
    }

    // Transposed pt column: one uint4 (8 halfs = 8 consecutive t) per block
    const bool canLoad = (i >= 0) && (i <= KIN - 1);
    const size_t col16 = ((size_t)b * KIN + (canLoad ? i : 0)) * TQ;  // halfs
    const uint4* ptcol = g_ptT + (col16 >> 3);
    uint4 rv4 = __ldg(ptcol);            // t = 1..8  (block 0)

    const bool owner = (lane >= KSTEP) && (i <= 400);
    const bool inR   = (i >= 0) && (i <= 400);

    const int NB  = (OL - 1) / KSTEP;
    const int rem = (OL - 1) - NB * KSTEP;
    int cb = 0;

    for (int blk = 0; blk < NB; blk++) {
        // prefetch next block first (max SB distance); always in-bounds
        const uint4 cur4 = rv4;
        rv4 = __ldg(ptcol + blk + 1);

        // unpack + mask (off critical chain)
        float pt[KSTEP];
        {
            const __half2* hh = reinterpret_cast<const __half2*>(&cur4);
            #pragma unroll
            for (int j = 0; j < 4; j++) {
                const float2 f = __half22float2(hh[j]);
                pt[2 * j]     = f.x * mk;
                pt[2 * j + 1] = f.y * mk;
            }
        }

        // log2 -> linear, per-warp renorm (64-state window)
        const float m = warp_fmax_redux(fmaxf(E, O));
        float el = ex2(E - m);
        float ol = ex2(O - m);

        // 8 linear steps (chain: shfl + add + fma)
        #pragma unroll
        for (int j = 0; j < KSTEP; j++) {
            const float prevO = __shfl_up_sync(0xffffffffu, ol, 1);
            const float h = el + prevO;
            ol = (h + ol) * pt[j];
            el = h * PB;
        }

        E = fmaxf(lg2(el) + m, ANEG);
        O = fmaxf(lg2(ol) + m, ANEG);

        if (owner) { Es[cb][i] = E; Os[cb][i] = O; }
        __syncthreads();
        E = inR ? Es[cb][i] : ANEG;
        O = inR ? Os[cb][i] : ANEG;
        cb ^= 1;
    }

    if (rem > 0) {    // ragged tail (t = 1+NB*KSTEP .. OL-1); rv4 holds them
        const float m = warp_fmax_redux(fmaxf(E, O));
        float el = ex2(E - m);
        float ol = ex2(O - m);
        const __half2* hh = reinterpret_cast<const __half2*>(&rv4);
        for (int j = 0; j < rem; j++) {
            const float2 f = __half22float2(hh[j >> 1]);
            const float pt = ((j & 1) ? f.y : f.x) * mk;
            const float prevO = __shfl_up_sync(0xffffffffu, ol, 1);
            const float h = el + prevO;
            ol = (h + ol) * pt;
            el = h * PB;
        }
        E = fmaxf(lg2(el) + m, ANEG);
        O = fmaxf(lg2(ol) + m, ANEG);
        if (owner) { Es[cb][i] = E; Os[cb][i] = O; }
        __syncthreads();
        cb ^= 1;
    }

    if (tid == 0) {
        const int fin = (rem > 0 || NB > 0) ? (cb ^ 1) : cb;
        const float aS   = Es[fin][L];       // state 2L
        const float aSm1 = Os[fin][L - 1];   // state 2L-1
        const float ll   = (lse2f(aS, aSm1) - Sval) * LN2;
        float loss = -ll / (float)L;
        if (!(ll > -1e6f) || !isfinite(loss)) loss = 0.f;
        g_losses[b] = loss;
    }
}

// ---------------------------------------------------------------------------
// Kernel 3: mean over batch -> scalar
// ---------------------------------------------------------------------------
__global__ void reduce_kernel(float* __restrict__ out, int B) {
    float s = 0.f;
    for (int k = threadIdx.x; k < B; k += 32) s += g_losses[k];
    #pragma unroll
    for (int o = 16; o; o >>= 1) s += __shfl_xor_sync(0xffffffffu, s, o);
    if (threadIdx.x == 0) out[0] = s / (float)B;
}

extern "C" void kernel_launch(void* const* d_in, const int* in_sizes, int n_in,
                              void* d_out, int out_size) {
    const float* attn     = (const float*)d_in[0];
    const int*   in_lens  = (const int*)d_in[1];
    const int*   out_lens = (const int*)d_in[2];
    int B = in_sizes[1];
    if (B > MAXB) B = MAXB;

    dim3 pgrid(NTILE, B);
    prep_kernel<<<pgrid, 256>>>(attn, in_lens, out_lens);
    ctc_kernel<<<B, NT>>>(attn, in_lens, out_lens);
    reduce_kernel<<<1, 32>>>((float*)d_out, B);
}

// round 15
// speedup vs baseline: 1.0204x; 1.0204x over previous
#include <cuda_runtime.h>
#include <cuda_fp16.h>
#include <math.h>

#define TQ    2000
#define KIN   400
#define MAXB  64
#define LOG2E 1.4426950408889634f
#define LN2   0.6931471805599453f
#define ANEG  (-1e7f)
#define PB    0.36787944117144233f  // e^{-1}

// ctc geometry (proven): 1 pair/thread, 64-state per-warp renorm window
#define KSTEP 8
#define PPW   24                    // owned pairs per warp
#define NW    17
#define NT    (NW * 32)             // 544

#define TTILE 16
#define NTILE 125                   // covers t = 1..1999
#define RS    408                   // smem halfs per row (8B-aligned rows)

__device__ float g_lse[MAXB * TQ];
// e^{attn} fp16 TRANSPOSED: half index = (b*KIN + col)*TQ + (t-1), t>=1
__device__ uint4 g_ptT[(size_t)MAXB * KIN * TQ / 8];
__device__ float g_losses[MAXB];

__device__ __forceinline__ float ex2(float x) {
    float r; asm("ex2.approx.ftz.f32 %0, %1;" : "=f"(r) : "f"(x)); return r;
}
__device__ __forceinline__ float lg2(float x) {
    float r; asm("lg2.approx.ftz.f32 %0, %1;" : "=f"(r) : "f"(x)); return r;
}
__device__ __forceinline__ float lse2f(float a, float b) {
    return fmaxf(a, b) + lg2(1.f + ex2(-fabsf(a - b)));
}

// ---------------------------------------------------------------------------
// Kernel 1: fused LSE + fp16 e^attn transposed table. Grid (NTILE, B), 256t.
// Warp w handles rows t1+2w, t1+2w+1 with float4 loads; tile 0 warp 0 also
// does the t=0 LSE. Phase 2 stores 16 t-values per column as 2x STG.128.
// ---------------------------------------------------------------------------
__global__ void prep_kernel(const float* __restrict__ attn,
                            const int* __restrict__ in_lens,
                            const int* __restrict__ out_lens) {
    __shared__ __half tile[TTILE][RS];
    const int b  = blockIdx.y;
    const int t1 = 1 + TTILE * blockIdx.x;
    const int OL = out_lens[b];
    const int L  = in_lens[b];
    const int w    = threadIdx.x >> 5;
    const int lane = threadIdx.x & 31;

    #pragma unroll
    for (int rr = 0; rr < 2; rr++) {
        const int r = w * 2 + rr;
        const int t = t1 + r;
        if (t <= TQ - 1 && t < OL) {
            const float4* row4 =
                (const float4*)(attn + ((size_t)b * TQ + t) * KIN);
            float s = 0.f;
            for (int k = lane; k < KIN / 4; k += 32) {
                const float4 v = __ldg(row4 + k);
                const float e0 = ex2(v.x * LOG2E);
                const float e1 = ex2(v.y * LOG2E);
                const float e2 = ex2(v.z * LOG2E);
                const float e3 = ex2(v.w * LOG2E);
                const __half2 h01 = __floats2half2_rn(e0, e1);
                const __half2 h23 = __floats2half2_rn(e2, e3);
                uint2 u;
                u.x = *reinterpret_cast<const unsigned*>(&h01);
                u.y = *reinterpret_cast<const unsigned*>(&h23);
                *reinterpret_cast<uint2*>(&tile[r][4 * k]) = u;
                const int base = 4 * k;
                s += (base + 0 < L ? e0 : 0.f) + (base + 1 < L ? e1 : 0.f)
                   + (base + 2 < L ? e2 : 0.f) + (base + 3 < L ? e3 : 0.f);
            }
            #pragma unroll
            for (int o = 16; o; o >>= 1) s += __shfl_xor_sync(0xffffffffu, s, o);
            if (lane == 0) g_lse[b * TQ + t] = lg2(s + PB);
        }
    }
    if (blockIdx.x == 0 && w == 0) {   // t = 0: lse only
        const float4* row4 = (const float4*)(attn + (size_t)b * TQ * KIN);
        float s = 0.f;
        for (int k = lane; k < KIN / 4; k += 32) {
            const float4 v = __ldg(row4 + k);
            const float e0 = ex2(v.x * LOG2E);
            const float e1 = ex2(v.y * LOG2E);
            const float e2 = ex2(v.z * LOG2E);
            const float e3 = ex2(v.w * LOG2E);
            const int base = 4 * k;
            s += (base + 0 < L ? e0 : 0.f) + (base + 1 < L ? e1 : 0.f)
               + (base + 2 < L ? e2 : 0.f) + (base + 3 < L ? e3 : 0.f);
        }
        #pragma unroll
        for (int o = 16; o; o >>= 1) s += __shfl_xor_sync(0xffffffffu, s, o);
        if (lane == 0) g_lse[b * TQ] = lg2(s + PB);
    }
    __syncthreads();

    for (int c = threadIdx.x; c < KIN; c += blockDim.x) {
        unsigned wd[8];
        #pragma unroll
        for (int j = 0; j < 8; j++) {
            const unsigned lo = __half_as_ushort(tile[2 * j][c]);
            const unsigned hi = __half_as_ushort(tile[2 * j + 1][c]);
            wd[j] = lo | (hi << 16);
        }
        const size_t halfbase = ((size_t)b * KIN + c) * TQ + (t1 - 1);
        uint4* dst = g_ptT + (halfbase >> 3);
        dst[0] = make_uint4(wd[0], wd[1], wd[2], wd[3]);
        dst[1] = make_uint4(wd[4], wd[5], wd[6], wd[7]);
    }
}

// ---------------------------------------------------------------------------
// Kernel 2: CTC forward recursion, alpha kept as (linear mantissa, per-warp
// int exponent A) across blocks — no log2 round-trip, ZERO inner/boundary
// MUFU. 544 threads, one pair (E=2i, O=2i+1) per thread; i = w*24+lane-8,
// lanes 0-7 halo. 8 linear steps per barrier. Renorm: signed-int REDUX over
// key = A_src + biased_exp(mant); rescale by power-of-two float; shift
// < -126 flushes to exact 0 (identical window semantics to the proven
// log2 scheme). Unnormalized: subtract S = sum lse2 at readout.
// ---------------------------------------------------------------------------
__global__ __launch_bounds__(NT, 1)
void ctc_kernel(const float* __restrict__ attn,
                const int* __restrict__ in_lens,
                const int* __restrict__ out_lens) {
    __shared__ float EsM[2][401];
    __shared__ float OsM[2][401];
    __shared__ int   AsM[2][NW];
    __shared__ float red[NW];

    const int b    = blockIdx.x;
    const int tid  = threadIdx.x;
    const int L    = in_lens[b];
    const int OL   = out_lens[b];
    const int w    = tid >> 5;
    const int lane = tid & 31;
    const int i    = w * PPW + lane - KSTEP;   // pair index [-8, 407]

    const float* lsebase = g_lse + b * TQ;

    // S = sum_{t<OL} lse2[t]
    {
        float s = 0.f;
        for (int t = tid; t < OL; t += NT) s += lsebase[t];
        #pragma unroll
        for (int o = 16; o; o >>= 1) s += __shfl_xor_sync(0xffffffffu, s, o);
        if (lane == 0) red[w] = s;
    }
    __syncthreads();
    float Sval = 0.f;
    if (tid == 0) {
        #pragma unroll
        for (int k = 0; k < NW; k++) Sval += red[k];
    }

    const float mk = ((i >= 0) && (i < L)) ? 1.f : 0.f;

    // init (linear): pair 0: E = e^{-1}, O = e^{x00}; A = 0
    float el = 0.f, ol = 0.f;
    int   A  = 0;
    if (i == 0) {
        el = PB;
        ol = ex2(__ldg(attn + (size_t)b * TQ * KIN) * LOG2E);
    }

    const bool canLoad = (i >= 0) && (i <= KIN - 1);
    const size_t col16 = ((size_t)b * KIN + (canLoad ? i : 0)) * TQ;
    const uint4* ptcol = g_ptT + (col16 >> 3);
    uint4 rv4 = __ldg(ptcol);            // t = 1..8

    const bool owner = (lane >= KSTEP) && (i <= 400);
    const bool inR   = (i >= 0) && (i <= 400);
    int srcw = (i >= 0) ? (i / PPW) : 0;             // warp owning pair i
    if (srcw > NW - 1) srcw = NW - 1;

    const int NB  = (OL - 1) / KSTEP;
    const int rem = (OL - 1) - NB * KSTEP;
    int cb = 0;

    for (int blk = 0; blk < NB; blk++) {
        const uint4 cur4 = rv4;
        rv4 = __ldg(ptcol + blk + 1);

        float pt[KSTEP];
        {
            const __half2* hh = reinterpret_cast<const __half2*>(&cur4);
            #pragma unroll
            for (int j = 0; j < 4; j++) {
                const float2 f = __half22float2(hh[j]);
                pt[2 * j]     = f.x * mk;
                pt[2 * j + 1] = f.y * mk;
            }
        }

        // 8 linear steps (chain: shfl + add + fma); values nonnegative
        #pragma unroll
        for (int j = 0; j < KSTEP; j++) {
            const float prevO = __shfl_up_sync(0xffffffffu, ol, 1);
            const float h = el + prevO;
            ol = (h + ol) * pt[j];
            el = h * PB;
        }

        // publish mantissas + warp exponent
        if (owner) { EsM[cb][i] = el; OsM[cb][i] = ol; }
        if (lane == 0) AsM[cb][w] = A;
        __syncthreads();
        el = inR ? EsM[cb][i] : 0.f;
        ol = inR ? OsM[cb][i] : 0.f;
        const int Al = AsM[cb][srcw];

        // exponent-domain renorm (no MUFU). key = A_src + biased_exp(mant)
        const int ke = (int)((__float_as_uint(el) >> 23) & 0xFFu);
        const int ko = (int)((__float_as_uint(ol) >> 23) & 0xFFu);
        const int key  = Al + (ke > ko ? ke : ko);
        const int kmax = __reduce_max_sync(0xffffffffu, key);  // signed max
        const int An   = kmax - 127;
        const int sft  = Al - An;                              // <= 127
        const float factor =
            (sft >= -126) ? __int_as_float((unsigned)(127 + sft) << 23) : 0.f;
        el *= factor;
        ol *= factor;
        A = An;
        cb ^= 1;
    }

    if (rem > 0) {   // ragged tail: t = 1+NB*KSTEP .. OL-1 (data in rv4)
        const __half2* hh = reinterpret_cast<const __half2*>(&rv4);
        for (int j = 0; j < rem; j++) {
            const float2 f = __half22float2(hh[j >> 1]);
            const float pt = ((j & 1) ? f.y : f.x) * mk;
            const float prevO = __shfl_up_sync(0xffffffffu, ol, 1);
            const float h = el + prevO;
            ol = (h + ol) * pt;
            el = h * PB;
        }
    }

    // final publish + readout
    if (owner) { EsM[cb][i] = el; OsM[cb][i] = ol; }
    if (lane == 0) AsM[cb][w] = A;
    __syncthreads();
    if (tid == 0) {
        const float m1 = EsM[cb][L];              // state 2L mantissa
        const int   A1 = AsM[cb][L / PPW];
        const float m2 = OsM[cb][L - 1];          // state 2L-1 mantissa
        const int   A2 = AsM[cb][(L - 1) / PPW];
        const float a1 = fmaxf(lg2(m1) + (float)A1, ANEG);
        const float a2 = fmaxf(lg2(m2) + (float)A2, ANEG);
        const float ll = (lse2f(a1, a2) - Sval) * LN2;
        float loss = -ll / (float)L;
        if (!(ll > -1e6f) || !isfinite(loss)) loss = 0.f;
        g_losses[b] = loss;
    }
}

// ---------------------------------------------------------------------------
// Kernel 3: mean over batch -> scalar
// ---------------------------------------------------------------------------
__global__ void reduce_kernel(float* __restrict__ out, int B) {
    float s = 0.f;
    for (int k = threadIdx.x; k < B; k += 32) s += g_losses[k];
    #pragma unroll
    for (int o = 16; o; o >>= 1) s += __shfl_xor_sync(0xffffffffu, s, o);
    if (threadIdx.x == 0) out[0] = s / (float)B;
}

extern "C" void kernel_launch(void* const* d_in, const int* in_sizes, int n_in,
                              void* d_out, int out_size) {
    const float* attn     = (const float*)d_in[0];
    const int*   in_lens  = (const int*)d_in[1];
    const int*   out_lens = (const int*)d_in[2];
    int B = in_sizes[1];
    if (B > MAXB) B = MAXB;

    dim3 pgrid(NTILE, B);
    prep_kernel<<<pgrid, 256>>>(attn, in_lens, out_lens);
    ctc_kernel<<<B, NT>>>(attn, in_lens, out_lens);
    reduce_kernel<<<1, 32>>>((float*)d_out, B);
}